// round 10
// baseline (speedup 1.0000x reference)
#include <cuda_runtime.h>

#define NN 50000
#define EE 800000
#define HD 128
#define NH 4
#define ND 32
#define GN 64          // nodes per gemm block
#define XROW (HD + 4)  // padded xs row (floats) to de-conflict x2 reads

typedef unsigned long long u64;

#define XS_BYTES (GN * XROW * 4)          // 33792
#define WS_BYTES (64 * HD * 8)            // 65536 (64 k2-rows x 128 u64)
#define SM_BYTES (XS_BYTES + WS_BYTES)    // 99328

// ---------------- scratch (device globals; no allocation allowed) ----------
__device__ float g_feat[NN * HD];   // Wh for current layer (25.6 MB)
__device__ float g_el[NN * NH];     // a_l . Wh
__device__ float g_er[NN * NH];     // a_r . Wh
__device__ float g_h1[NN * HD];     // layer-1 output (post-ELU) (25.6 MB)
__device__ float g_e[EE * NH];      // exp(e) spill for deg>32 nodes (12.8 MB)
__device__ int   g_dsti[EE];        // decoded int32 dst (3.2 MB)
__device__ int   g_csr_src[EE];     // src ids sorted by dst (3.2 MB)
__device__ int   g_cnt[NN];         // degree histogram, then scatter cursors
__device__ int   g_off[NN + 1];     // CSR offsets (by dst)
__device__ int   g_is64;            // 1 if src/dst stored as int64

// ---------------- helpers ---------------------------------------------------
__device__ __forceinline__ float lrelu(float x) {
    return (x > 0.f) ? x : 0.2f * x;
}
__device__ __forceinline__ u64 fma2(u64 a, u64 b, u64 c) {
    u64 d;
    asm("fma.rn.f32x2 %0, %1, %2, %3;" : "=l"(d) : "l"(a), "l"(b), "l"(c));
    return d;
}
__device__ __forceinline__ float sum2(u64 a) {
    float lo, hi;
    asm("mov.b64 {%0, %1}, %2;" : "=f"(lo), "=f"(hi) : "l"(a));
    return lo + hi;
}
__device__ __forceinline__ u64 pack2(float lo, float hi) {
    u64 d;
    asm("mov.b64 %0, {%1, %2};" : "=l"(d) : "f"(lo), "f"(hi));
    return d;
}

// ---------------- CSR build --------------------------------------------------
__global__ void zero_cnt_kernel(const long long* __restrict__ src) {
    int i = blockIdx.x * blockDim.x + threadIdx.x;
    if (i < NN) g_cnt[i] = 0;
    if (i == 0) {
        bool is64 = true;
        for (int k = 0; k < 8; k++) {
            long long v = src[k];
            if (v < 0 || v >= NN) { is64 = false; break; }
        }
        g_is64 = is64 ? 1 : 0;
    }
}

// decode dst + degree histogram: 4 edges per thread
__global__ void convert_kernel(const void* __restrict__ dst) {
    int e0 = (blockIdx.x * blockDim.x + threadIdx.x) * 4;
    if (e0 >= EE) return;
    int t[4];
    if (g_is64) {
        const longlong2* p = (const longlong2*)((const long long*)dst + e0);
        longlong2 a = p[0], b = p[1];
        t[0] = (int)a.x; t[1] = (int)a.y; t[2] = (int)b.x; t[3] = (int)b.y;
    } else {
        int4 a = *(const int4*)((const int*)dst + e0);
        t[0] = a.x; t[1] = a.y; t[2] = a.z; t[3] = a.w;
    }
    *(int4*)(g_dsti + e0) = make_int4(t[0], t[1], t[2], t[3]);
#pragma unroll
    for (int k = 0; k < 4; k++) atomicAdd(&g_cnt[t[k]], 1);
}

// single-block fused exclusive scan over g_cnt -> g_off (+ cursor init)
#define STB 1024
__global__ void __launch_bounds__(STB) scan_fused_kernel() {
    __shared__ int sd[STB];
    const int tid = threadIdx.x;
    const int per = (NN + STB - 1) / STB;          // 49
    const int start = tid * per;
    const int end = (start + per < NN) ? start + per : NN;

    int s = 0;
    for (int i = start; i < end; i++) s += g_cnt[i];
    sd[tid] = s;
    __syncthreads();
    for (int off = 1; off < STB; off <<= 1) {
        int t = (tid >= off) ? sd[tid - off] : 0;
        __syncthreads();
        sd[tid] += t;
        __syncthreads();
    }
    int run = sd[tid] - s;                          // exclusive base
    for (int i = start; i < end; i++) {
        int v = g_cnt[i];
        g_off[i] = run;
        g_cnt[i] = run;                             // becomes scatter cursor
        run += v;
    }
    if (tid == 0) g_off[NN] = EE;
}

// scatter src ids into CSR slots: 4 edges per thread
__global__ void scatter_kernel(const void* __restrict__ src) {
    int e0 = (blockIdx.x * blockDim.x + threadIdx.x) * 4;
    if (e0 >= EE) return;
    int s[4];
    if (g_is64) {
        const longlong2* p = (const longlong2*)((const long long*)src + e0);
        longlong2 a = p[0], b = p[1];
        s[0] = (int)a.x; s[1] = (int)a.y; s[2] = (int)b.x; s[3] = (int)b.y;
    } else {
        int4 a = *(const int4*)((const int*)src + e0);
        s[0] = a.x; s[1] = a.y; s[2] = a.z; s[3] = a.w;
    }
    int4 t = *(const int4*)(g_dsti + e0);
    int tt[4] = {t.x, t.y, t.z, t.w};
#pragma unroll
    for (int k = 0; k < 4; k++) {
        int pos = atomicAdd(&g_cnt[tt[k]], 1);
        g_csr_src[pos] = s[k];
    }
}

// ---------------- GEMM: feat = x @ W^T (register-tiled, packed-k fma2) ------
// Block: 64 nodes x 128 cols, 256 threads = 16(tx) x 16(ty). Thread computes
// 4 nodes x 8 cols (j = tx + 16*jj). Accumulators are k-paired f32x2.
// ALL of W staged once in smem, transposed as u64 (k,k+1) pairs, XOR-swizzled
// ws2[k2][j ^ (k2&15)]. X tile row-padded. Exactly 2 __syncthreads total.
// xin == nullptr means "read layer-1 output g_h1".
__global__ void __launch_bounds__(256, 2) gemm_kernel(
    const float* __restrict__ xin, const float* __restrict__ W,
    const float* __restrict__ al, const float* __restrict__ ar)
{
    extern __shared__ __align__(16) char smbuf[];
    float (*xs)[XROW] = (float(*)[XROW])smbuf;
    u64 (*ws2)[HD] = (u64(*)[HD])(smbuf + XS_BYTES);

    const float* xp = xin ? xin : (const float*)g_h1;
    const int tid = threadIdx.x;
    const int tx = tid & 15;
    const int ty = tid >> 4;
    const int node0 = blockIdx.x * GN;

    // ---- load X tile: 64 rows x 128 floats (2048 float4, 8 per thread) ----
    for (int it = 0; it < 8; it++) {
        int idx = it * 256 + tid;
        int row = idx >> 5, c4 = idx & 31;
        int node = node0 + row;
        float4 v = (node < NN) ? ((const float4*)xp)[(size_t)node * 32 + c4]
                               : make_float4(0.f, 0.f, 0.f, 0.f);
        *(float4*)&xs[row][c4 * 4] = v;
    }
    // ---- load ALL of W: 128 rows x 32 float4 (4096 float4, 16 per thread) --
    for (int it = 0; it < 16; it++) {
        int idx = it * 256 + tid;
        int j = idx >> 5, c = idx & 31;            // c = float4 index in row
        float4 v = ((const float4*)W)[j * 32 + c];
        int k2a = c * 2, k2b = k2a + 1;
        ws2[k2a][j ^ (k2a & 15)] = pack2(v.x, v.y);
        ws2[k2b][j ^ (k2b & 15)] = pack2(v.z, v.w);
    }

    u64 acc2[4][8];
#pragma unroll
    for (int i = 0; i < 4; i++)
#pragma unroll
        for (int jj = 0; jj < 8; jj++) acc2[i][jj] = 0ull;

    __syncthreads();

    // ---- compute: 64 k2 steps, no barriers ----
#pragma unroll 8
    for (int q = 0; q < 64; q++) {
        const int qm = q & 15;
        u64 w2[8];
#pragma unroll
        for (int jj = 0; jj < 8; jj++)
            w2[jj] = ws2[q][(tx + 16 * jj) ^ qm];
#pragma unroll
        for (int i = 0; i < 4; i++) {
            u64 x2 = *(const u64*)&xs[ty * 4 + i][q * 2];
#pragma unroll
            for (int jj = 0; jj < 8; jj++)
                acc2[i][jj] = fma2(x2, w2[jj], acc2[i][jj]);
        }
    }

    // ---- fold k-pairs, store feat, compute el/er ----
    float a_l[8], a_r[8];
#pragma unroll
    for (int jj = 0; jj < 8; jj++) {
        a_l[jj] = __ldg(&al[tx + 16 * jj]);
        a_r[jj] = __ldg(&ar[tx + 16 * jj]);
    }

#pragma unroll
    for (int i = 0; i < 4; i++) {
        int node = node0 + ty * 4 + i;
        float f[8];
#pragma unroll
        for (int jj = 0; jj < 8; jj++) f[jj] = sum2(acc2[i][jj]);
        if (node < NN) {
#pragma unroll
            for (int jj = 0; jj < 8; jj++)
                g_feat[(size_t)node * HD + tx + 16 * jj] = f[jj];
        }
        // head h owns jj = 2h, 2h+1  (j = tx+32h and tx+16+32h)
        float elp[4], erp[4];
#pragma unroll
        for (int h = 0; h < 4; h++) {
            elp[h] = f[2 * h] * a_l[2 * h] + f[2 * h + 1] * a_l[2 * h + 1];
            erp[h] = f[2 * h] * a_r[2 * h] + f[2 * h + 1] * a_r[2 * h + 1];
        }
        // reduce across the 16 tx lanes (xor offsets < 16 stay in half-warp)
#pragma unroll
        for (int off = 8; off; off >>= 1) {
#pragma unroll
            for (int h = 0; h < 4; h++) {
                elp[h] += __shfl_xor_sync(0xffffffffu, elp[h], off);
                erp[h] += __shfl_xor_sync(0xffffffffu, erp[h], off);
            }
        }
        if (tx == 0 && node < NN) {
#pragma unroll
            for (int h = 0; h < 4; h++) {
                g_el[node * NH + h] = elp[h];
                g_er[node * NH + h] = erp[h];
            }
        }
    }
}

// ---------------- fused edge softmax + aggregate (warp per dst node) --------
// Softmax without max subtraction (|e| is small; exp(e)/sum(exp(e)) matches
// the reference value mathematically).
__global__ void __launch_bounds__(256) gat_edge_kernel(float* __restrict__ out)
{
    __shared__ int   ssrc[8][32];
    __shared__ float salpha[8][32][4];

    const int w = threadIdx.x >> 5;
    int t = blockIdx.x * 8 + w;
    if (t >= NN) return;
    const int lane = threadIdx.x & 31;
    const int beg = g_off[t], end = g_off[t + 1];
    const int deg = end - beg;
    const int h = lane >> 3;

    float4 acc = {0.f, 0.f, 0.f, 0.f};

    if (deg > 0) {
        float4 er4 = *(const float4*)(g_er + t * NH);  // broadcast
        const bool small = (deg <= 32);

        // ---- phase 1: ex = exp(lrelu(el+er)); sum denominators ----
        float4 d4 = {0.f, 0.f, 0.f, 0.f};
        int s_my = 0;
        float4 ex_my = {0.f, 0.f, 0.f, 0.f};

        int i0 = beg + lane;
        if (i0 < end) {
            s_my = __ldg(&g_csr_src[i0]);
            float4 l4 = *(const float4*)(g_el + s_my * NH);
            ex_my.x = __expf(lrelu(l4.x + er4.x));
            ex_my.y = __expf(lrelu(l4.y + er4.y));
            ex_my.z = __expf(lrelu(l4.z + er4.z));
            ex_my.w = __expf(lrelu(l4.w + er4.w));
            d4 = ex_my;
            if (!small) *(float4*)(g_e + (size_t)i0 * NH) = ex_my;
        }
        if (!small) {
            for (int i = i0 + 32; i < end; i += 32) {
                int s = __ldg(&g_csr_src[i]);
                float4 l4 = *(const float4*)(g_el + s * NH);
                float4 ex;
                ex.x = __expf(lrelu(l4.x + er4.x));
                ex.y = __expf(lrelu(l4.y + er4.y));
                ex.z = __expf(lrelu(l4.z + er4.z));
                ex.w = __expf(lrelu(l4.w + er4.w));
                d4.x += ex.x; d4.y += ex.y; d4.z += ex.z; d4.w += ex.w;
                *(float4*)(g_e + (size_t)i * NH) = ex;
            }
        }
#pragma unroll
        for (int off = 16; off; off >>= 1) {
            d4.x += __shfl_xor_sync(0xffffffffu, d4.x, off);
            d4.y += __shfl_xor_sync(0xffffffffu, d4.y, off);
            d4.z += __shfl_xor_sync(0xffffffffu, d4.z, off);
            d4.w += __shfl_xor_sync(0xffffffffu, d4.w, off);
        }
        float4 rd4;
        rd4.x = __frcp_rn(d4.x); rd4.y = __frcp_rn(d4.y);
        rd4.z = __frcp_rn(d4.z); rd4.w = __frcp_rn(d4.w);

        // ---- phase 2: aggregation via smem-staged (src, alpha) ----
        if (small) {
            if (lane < deg) {
                ssrc[w][lane] = s_my;
                salpha[w][lane][0] = ex_my.x * rd4.x;
                salpha[w][lane][1] = ex_my.y * rd4.y;
                salpha[w][lane][2] = ex_my.z * rd4.z;
                salpha[w][lane][3] = ex_my.w * rd4.w;
            }
            __syncwarp();
            for (int i = 0; i < deg; i++) {
                int si = ssrc[w][i];
                float alpha = salpha[w][i][h];
                float4 f = *(const float4*)(g_feat + (size_t)si * HD + lane * 4);
                acc.x = fmaf(f.x, alpha, acc.x);
                acc.y = fmaf(f.y, alpha, acc.y);
                acc.z = fmaf(f.z, alpha, acc.z);
                acc.w = fmaf(f.w, alpha, acc.w);
            }
        } else {
            for (int base = beg; base < end; base += 32) {
                int n = min(32, end - base);
                if (lane < n) {
                    int i = base + lane;
                    int s = __ldg(&g_csr_src[i]);
                    float4 ex = *(const float4*)(g_e + (size_t)i * NH);
                    ssrc[w][lane] = s;
                    salpha[w][lane][0] = ex.x * rd4.x;
                    salpha[w][lane][1] = ex.y * rd4.y;
                    salpha[w][lane][2] = ex.z * rd4.z;
                    salpha[w][lane][3] = ex.w * rd4.w;
                }
                __syncwarp();
                for (int i = 0; i < n; i++) {
                    int si = ssrc[w][i];
                    float alpha = salpha[w][i][h];
                    float4 f = *(const float4*)(g_feat + (size_t)si * HD + lane * 4);
                    acc.x = fmaf(f.x, alpha, acc.x);
                    acc.y = fmaf(f.y, alpha, acc.y);
                    acc.z = fmaf(f.z, alpha, acc.z);
                    acc.w = fmaf(f.w, alpha, acc.w);
                }
                __syncwarp();
            }
        }
    }

    // ---- epilogue: ELU (+ head-mean for layer 2) ----
    acc.x = (acc.x > 0.f) ? acc.x : expm1f(acc.x);
    acc.y = (acc.y > 0.f) ? acc.y : expm1f(acc.y);
    acc.z = (acc.z > 0.f) ? acc.z : expm1f(acc.z);
    acc.w = (acc.w > 0.f) ? acc.w : expm1f(acc.w);

    if (out == nullptr) {
        *(float4*)(g_h1 + (size_t)t * HD + lane * 4) = acc;
    } else {
#pragma unroll
        for (int off = 8; off <= 16; off <<= 1) {
            acc.x += __shfl_xor_sync(0xffffffffu, acc.x, off);
            acc.y += __shfl_xor_sync(0xffffffffu, acc.y, off);
            acc.z += __shfl_xor_sync(0xffffffffu, acc.z, off);
            acc.w += __shfl_xor_sync(0xffffffffu, acc.w, off);
        }
        if (lane < 8) {
            float4 o;
            o.x = 0.25f * acc.x; o.y = 0.25f * acc.y;
            o.z = 0.25f * acc.z; o.w = 0.25f * acc.w;
            *(float4*)(out + t * ND + lane * 4) = o;
        }
    }
}

// ---------------- launch ----------------------------------------------------
extern "C" void kernel_launch(void* const* d_in, const int* in_sizes, int n_in,
                              void* d_out, int out_size)
{
    const float* x   = (const float*)d_in[0];
    const void*  src = d_in[1];
    const void*  dst = d_in[2];
    const float* W1  = (const float*)d_in[3];
    const float* al1 = (const float*)d_in[4];
    const float* ar1 = (const float*)d_in[5];
    const float* W2  = (const float*)d_in[6];
    const float* al2 = (const float*)d_in[7];
    const float* ar2 = (const float*)d_in[8];
    float* out = (float*)d_out;

    const int edge4_blocks = (EE / 4 + 255) / 256;   // EE divisible by 4
    const int node_blocks = (NN + 255) / 256;
    const int gemm_blocks = (NN + GN - 1) / GN;      // 782
    const int gat_blocks  = (NN + 7) / 8;

    cudaFuncSetAttribute(gemm_kernel,
                         cudaFuncAttributeMaxDynamicSharedMemorySize, SM_BYTES);

    zero_cnt_kernel<<<node_blocks, 256>>>((const long long*)src);
    convert_kernel<<<edge4_blocks, 256>>>(dst);
    scan_fused_kernel<<<1, STB>>>();
    gemm_kernel<<<gemm_blocks, 256, SM_BYTES>>>(x, W1, al1, ar1);
    scatter_kernel<<<edge4_blocks, 256>>>(src);

    gat_edge_kernel<<<gat_blocks, 256>>>(nullptr);

    gemm_kernel<<<gemm_blocks, 256, SM_BYTES>>>(nullptr, W2, al2, ar2);
    gat_edge_kernel<<<gat_blocks, 256>>>(out);

    (void)in_sizes; (void)n_in; (void)out_size;
}

// round 14
// speedup vs baseline: 1.6671x; 1.6671x over previous
#include <cuda_runtime.h>

#define NN 50000
#define EE 800000
#define HD 128
#define NH 4
#define ND 32
#define GN 64           // nodes per gemm block
#define XROW 132        // padded row (floats): 33 x 16B (odd) -> conflict-free

typedef unsigned long long u64;

#define XS_BYTES (GN * XROW * 4)          // 33792
#define WS_BYTES (HD * XROW * 4)          // 67584
#define SM_BYTES (XS_BYTES + WS_BYTES)    // 101376

// ---------------- scratch (device globals; no allocation allowed) ----------
__device__ float g_feat[NN * HD];   // Wh for current layer (25.6 MB)
__device__ float g_el[NN * NH];     // a_l . Wh
__device__ float g_er[NN * NH];     // a_r . Wh
__device__ float g_h1[NN * HD];     // layer-1 output (post-ELU) (25.6 MB)
__device__ float g_e[EE * NH];      // exp(e) spill for deg>32 nodes (12.8 MB)
__device__ int   g_dsti[EE];        // decoded int32 dst (3.2 MB)
__device__ int   g_csr_src[EE];     // src ids sorted by dst (3.2 MB)
__device__ int   g_cnt[NN];         // degree histogram, then scatter cursors
__device__ int   g_off[NN + 1];     // CSR offsets (by dst)
__device__ int   g_is64;            // 1 if src/dst stored as int64

// ---------------- helpers ---------------------------------------------------
__device__ __forceinline__ float lrelu(float x) {
    return (x > 0.f) ? x : 0.2f * x;
}
__device__ __forceinline__ u64 fma2(u64 a, u64 b, u64 c) {
    u64 d;
    asm("fma.rn.f32x2 %0, %1, %2, %3;" : "=l"(d) : "l"(a), "l"(b), "l"(c));
    return d;
}
__device__ __forceinline__ float sum2(u64 a) {
    float lo, hi;
    asm("mov.b64 {%0, %1}, %2;" : "=f"(lo), "=f"(hi) : "l"(a));
    return lo + hi;
}

// ---------------- CSR build (proven R9 versions) -----------------------------
__global__ void zero_cnt_kernel(const long long* __restrict__ src) {
    int i = blockIdx.x * blockDim.x + threadIdx.x;
    if (i < NN) g_cnt[i] = 0;
    if (i == 0) {
        bool is64 = true;
        for (int k = 0; k < 8; k++) {
            long long v = src[k];
            if (v < 0 || v >= NN) { is64 = false; break; }
        }
        g_is64 = is64 ? 1 : 0;
    }
}

__global__ void convert_kernel(const void* __restrict__ dst) {
    int e = blockIdx.x * blockDim.x + threadIdx.x;
    if (e >= EE) return;
    int t = g_is64 ? (int)((const long long*)dst)[e] : ((const int*)dst)[e];
    g_dsti[e] = t;
    atomicAdd(&g_cnt[t], 1);
}

#define STB 1024
__global__ void __launch_bounds__(STB) scan_fused_kernel() {
    __shared__ int sd[STB];
    const int tid = threadIdx.x;
    const int per = (NN + STB - 1) / STB;          // 49
    const int start = tid * per;
    const int end = (start + per < NN) ? start + per : NN;

    int s = 0;
    for (int i = start; i < end; i++) s += g_cnt[i];
    sd[tid] = s;
    __syncthreads();
    for (int off = 1; off < STB; off <<= 1) {
        int t = (tid >= off) ? sd[tid - off] : 0;
        __syncthreads();
        sd[tid] += t;
        __syncthreads();
    }
    int run = sd[tid] - s;                          // exclusive base
    for (int i = start; i < end; i++) {
        int v = g_cnt[i];
        g_off[i] = run;
        g_cnt[i] = run;                             // becomes scatter cursor
        run += v;
    }
    if (tid == 0) g_off[NN] = EE;
}

__global__ void scatter_kernel(const void* __restrict__ src) {
    int e = blockIdx.x * blockDim.x + threadIdx.x;
    if (e >= EE) return;
    int s = g_is64 ? (int)((const long long*)src)[e] : ((const int*)src)[e];
    int t = g_dsti[e];
    int pos = atomicAdd(&g_cnt[t], 1);
    g_csr_src[pos] = s;
}

// ---------------- GEMM: feat = x @ W^T (LDS.128, packed-k fma2) --------------
// Block: 64 nodes x 128 cols, 256 threads = 16(tx) x 16(ty). Thread computes
// 4 nodes x 8 cols (j = tx + 16*jj). Accumulators are k-paired f32x2.
// W staged ONCE in smem in natural [j][k] layout (straight float4 copy),
// rows padded to 132 floats (33x16B, odd) -> LDS.128 reads conflict-free.
// Per 4-k step: 12 LDS.128 + 64 fma2 (half the LDS of the R9 kernel).
// xin == nullptr means "read layer-1 output g_h1".
__global__ void __launch_bounds__(256, 2) gemm_kernel(
    const float* __restrict__ xin, const float* __restrict__ W,
    const float* __restrict__ al, const float* __restrict__ ar)
{
    extern __shared__ __align__(16) char smbuf[];
    float* xs = (float*)smbuf;                  // [GN][XROW]
    float* ws = (float*)(smbuf + XS_BYTES);     // [HD][XROW]

    const float* xp = xin ? xin : (const float*)g_h1;
    const int tid = threadIdx.x;
    const int tx = tid & 15;
    const int ty = tid >> 4;
    const int node0 = blockIdx.x * GN;

    // ---- load X tile: 64 rows x 32 float4 (8 per thread) ----
    for (int it = 0; it < 8; it++) {
        int idx = it * 256 + tid;
        int row = idx >> 5, c4 = idx & 31;
        int node = node0 + row;
        float4 v = (node < NN) ? ((const float4*)xp)[(size_t)node * 32 + c4]
                               : make_float4(0.f, 0.f, 0.f, 0.f);
        *(float4*)&xs[row * XROW + c4 * 4] = v;
    }
    // ---- load ALL of W: 128 rows x 32 float4 (16 per thread), no transform --
    for (int it = 0; it < 16; it++) {
        int idx = it * 256 + tid;
        int j = idx >> 5, c = idx & 31;
        *(float4*)&ws[j * XROW + c * 4] = ((const float4*)W)[j * 32 + c];
    }

    u64 acc2[4][8];
#pragma unroll
    for (int i = 0; i < 4; i++)
#pragma unroll
        for (int jj = 0; jj < 8; jj++) acc2[i][jj] = 0ull;

    __syncthreads();

    // ---- compute: 32 q4 steps (4 k each), no barriers ----
#pragma unroll 4
    for (int q4 = 0; q4 < 32; q4++) {
        ulonglong2 x2[4];
#pragma unroll
        for (int i = 0; i < 4; i++)
            x2[i] = *(const ulonglong2*)&xs[(ty * 4 + i) * XROW + q4 * 4];
#pragma unroll
        for (int jj = 0; jj < 8; jj++) {
            ulonglong2 w2 = *(const ulonglong2*)&ws[(tx + 16 * jj) * XROW + q4 * 4];
#pragma unroll
            for (int i = 0; i < 4; i++) {
                acc2[i][jj] = fma2(x2[i].x, w2.x, acc2[i][jj]);
                acc2[i][jj] = fma2(x2[i].y, w2.y, acc2[i][jj]);
            }
        }
    }

    // ---- fold k-pairs, store feat, compute el/er (R9 epilogue) ----
    float a_l[8], a_r[8];
#pragma unroll
    for (int jj = 0; jj < 8; jj++) {
        a_l[jj] = __ldg(&al[tx + 16 * jj]);
        a_r[jj] = __ldg(&ar[tx + 16 * jj]);
    }

#pragma unroll
    for (int i = 0; i < 4; i++) {
        int node = node0 + ty * 4 + i;
        float f[8];
#pragma unroll
        for (int jj = 0; jj < 8; jj++) f[jj] = sum2(acc2[i][jj]);
        if (node < NN) {
#pragma unroll
            for (int jj = 0; jj < 8; jj++)
                g_feat[(size_t)node * HD + tx + 16 * jj] = f[jj];
        }
        // head h owns jj = 2h, 2h+1  (j = tx+32h and tx+16+32h)
        float elp[4], erp[4];
#pragma unroll
        for (int h = 0; h < 4; h++) {
            elp[h] = f[2 * h] * a_l[2 * h] + f[2 * h + 1] * a_l[2 * h + 1];
            erp[h] = f[2 * h] * a_r[2 * h] + f[2 * h + 1] * a_r[2 * h + 1];
        }
#pragma unroll
        for (int off = 8; off; off >>= 1) {
#pragma unroll
            for (int h = 0; h < 4; h++) {
                elp[h] += __shfl_xor_sync(0xffffffffu, elp[h], off);
                erp[h] += __shfl_xor_sync(0xffffffffu, erp[h], off);
            }
        }
        if (tx == 0 && node < NN) {
#pragma unroll
            for (int h = 0; h < 4; h++) {
                g_el[node * NH + h] = elp[h];
                g_er[node * NH + h] = erp[h];
            }
        }
    }
}

// ---------------- fused edge softmax + aggregate (warp per dst node) --------
__global__ void __launch_bounds__(256) gat_edge_kernel(float* __restrict__ out)
{
    __shared__ int   ssrc[8][32];
    __shared__ float salpha[8][32][4];

    const int w = threadIdx.x >> 5;
    int t = blockIdx.x * 8 + w;
    if (t >= NN) return;
    const int lane = threadIdx.x & 31;
    const int beg = g_off[t], end = g_off[t + 1];
    const int deg = end - beg;
    const int h = lane >> 3;

    float4 acc = {0.f, 0.f, 0.f, 0.f};

    if (deg > 0) {
        float4 er4 = *(const float4*)(g_er + t * NH);  // broadcast
        const bool small = (deg <= 32);

        // ---- phase 1: ex = exp(lrelu(el+er)); sum denominators ----
        float4 d4 = {0.f, 0.f, 0.f, 0.f};
        int s_my = 0;
        float4 ex_my = {0.f, 0.f, 0.f, 0.f};

        int i0 = beg + lane;
        if (i0 < end) {
            s_my = __ldg(&g_csr_src[i0]);
            float4 l4 = *(const float4*)(g_el + s_my * NH);
            ex_my.x = __expf(lrelu(l4.x + er4.x));
            ex_my.y = __expf(lrelu(l4.y + er4.y));
            ex_my.z = __expf(lrelu(l4.z + er4.z));
            ex_my.w = __expf(lrelu(l4.w + er4.w));
            d4 = ex_my;
            if (!small) *(float4*)(g_e + (size_t)i0 * NH) = ex_my;
        }
        if (!small) {
            for (int i = i0 + 32; i < end; i += 32) {
                int s = __ldg(&g_csr_src[i]);
                float4 l4 = *(const float4*)(g_el + s * NH);
                float4 ex;
                ex.x = __expf(lrelu(l4.x + er4.x));
                ex.y = __expf(lrelu(l4.y + er4.y));
                ex.z = __expf(lrelu(l4.z + er4.z));
                ex.w = __expf(lrelu(l4.w + er4.w));
                d4.x += ex.x; d4.y += ex.y; d4.z += ex.z; d4.w += ex.w;
                *(float4*)(g_e + (size_t)i * NH) = ex;
            }
        }
#pragma unroll
        for (int off = 16; off; off >>= 1) {
            d4.x += __shfl_xor_sync(0xffffffffu, d4.x, off);
            d4.y += __shfl_xor_sync(0xffffffffu, d4.y, off);
            d4.z += __shfl_xor_sync(0xffffffffu, d4.z, off);
            d4.w += __shfl_xor_sync(0xffffffffu, d4.w, off);
        }
        float4 rd4;
        rd4.x = __frcp_rn(d4.x); rd4.y = __frcp_rn(d4.y);
        rd4.z = __frcp_rn(d4.z); rd4.w = __frcp_rn(d4.w);

        // ---- phase 2: aggregation via smem-staged (src, alpha) ----
        if (small) {
            if (lane < deg) {
                ssrc[w][lane] = s_my;
                salpha[w][lane][0] = ex_my.x * rd4.x;
                salpha[w][lane][1] = ex_my.y * rd4.y;
                salpha[w][lane][2] = ex_my.z * rd4.z;
                salpha[w][lane][3] = ex_my.w * rd4.w;
            }
            __syncwarp();
            for (int i = 0; i < deg; i++) {
                int si = ssrc[w][i];
                float alpha = salpha[w][i][h];
                float4 f = *(const float4*)(g_feat + (size_t)si * HD + lane * 4);
                acc.x = fmaf(f.x, alpha, acc.x);
                acc.y = fmaf(f.y, alpha, acc.y);
                acc.z = fmaf(f.z, alpha, acc.z);
                acc.w = fmaf(f.w, alpha, acc.w);
            }
        } else {
            for (int base = beg; base < end; base += 32) {
                int n = min(32, end - base);
                if (lane < n) {
                    int i = base + lane;
                    int s = __ldg(&g_csr_src[i]);
                    float4 ex = *(const float4*)(g_e + (size_t)i * NH);
                    ssrc[w][lane] = s;
                    salpha[w][lane][0] = ex.x * rd4.x;
                    salpha[w][lane][1] = ex.y * rd4.y;
                    salpha[w][lane][2] = ex.z * rd4.z;
                    salpha[w][lane][3] = ex.w * rd4.w;
                }
                __syncwarp();
                for (int i = 0; i < n; i++) {
                    int si = ssrc[w][i];
                    float alpha = salpha[w][i][h];
                    float4 f = *(const float4*)(g_feat + (size_t)si * HD + lane * 4);
                    acc.x = fmaf(f.x, alpha, acc.x);
                    acc.y = fmaf(f.y, alpha, acc.y);
                    acc.z = fmaf(f.z, alpha, acc.z);
                    acc.w = fmaf(f.w, alpha, acc.w);
                }
                __syncwarp();
            }
        }
    }

    // ---- epilogue: ELU (+ head-mean for layer 2) ----
    acc.x = (acc.x > 0.f) ? acc.x : expm1f(acc.x);
    acc.y = (acc.y > 0.f) ? acc.y : expm1f(acc.y);
    acc.z = (acc.z > 0.f) ? acc.z : expm1f(acc.z);
    acc.w = (acc.w > 0.f) ? acc.w : expm1f(acc.w);

    if (out == nullptr) {
        *(float4*)(g_h1 + (size_t)t * HD + lane * 4) = acc;
    } else {
#pragma unroll
        for (int off = 8; off <= 16; off <<= 1) {
            acc.x += __shfl_xor_sync(0xffffffffu, acc.x, off);
            acc.y += __shfl_xor_sync(0xffffffffu, acc.y, off);
            acc.z += __shfl_xor_sync(0xffffffffu, acc.z, off);
            acc.w += __shfl_xor_sync(0xffffffffu, acc.w, off);
        }
        if (lane < 8) {
            float4 o;
            o.x = 0.25f * acc.x; o.y = 0.25f * acc.y;
            o.z = 0.25f * acc.z; o.w = 0.25f * acc.w;
            *(float4*)(out + t * ND + lane * 4) = o;
        }
    }
}

// ---------------- launch ----------------------------------------------------
extern "C" void kernel_launch(void* const* d_in, const int* in_sizes, int n_in,
                              void* d_out, int out_size)
{
    const float* x   = (const float*)d_in[0];
    const void*  src = d_in[1];
    const void*  dst = d_in[2];
    const float* W1  = (const float*)d_in[3];
    const float* al1 = (const float*)d_in[4];
    const float* ar1 = (const float*)d_in[5];
    const float* W2  = (const float*)d_in[6];
    const float* al2 = (const float*)d_in[7];
    const float* ar2 = (const float*)d_in[8];
    float* out = (float*)d_out;

    const int edge_blocks = (EE + 255) / 256;
    const int node_blocks = (NN + 255) / 256;
    const int gemm_blocks = (NN + GN - 1) / GN;      // 782
    const int gat_blocks  = (NN + 7) / 8;

    cudaFuncSetAttribute(gemm_kernel,
                         cudaFuncAttributeMaxDynamicSharedMemorySize, SM_BYTES);

    zero_cnt_kernel<<<node_blocks, 256>>>((const long long*)src);
    convert_kernel<<<edge_blocks, 256>>>(dst);
    scan_fused_kernel<<<1, STB>>>();
    gemm_kernel<<<gemm_blocks, 256, SM_BYTES>>>(x, W1, al1, ar1);
    scatter_kernel<<<edge_blocks, 256>>>(src);

    gat_edge_kernel<<<gat_blocks, 256>>>(nullptr);

    gemm_kernel<<<gemm_blocks, 256, SM_BYTES>>>(nullptr, W2, al2, ar2);
    gat_edge_kernel<<<gat_blocks, 256>>>(out);

    (void)in_sizes; (void)n_in; (void)out_size;
}